// round 11
// baseline (speedup 1.0000x reference)
#include <cuda_runtime.h>

// SphericalBessel, Miller downward recurrence in scaled variable
//   S_l = j_l * (x*sigma)^(-l),  sigma = exact per-thread power of two.
// Branch-free recurrence  S_{l-1} = (2l+1)*sigma*S_l - (x*sigma)^2*S_{l+1},
// double-single (unnormalized pair) arithmetic, register taps (R5 core).
//
// R11: PERSISTENT grid = 740 blocks (5 resident/SM on 148 SMs), each
// grid-striding over the 8192 n-chunks -> single wave, no inter-wave drain
// (was ~11 waves => ~9% tail loss). r for the next chunk is prefetched
// before the epilogue. norm*z^l chain split even/odd to halve its latency.
//
// Thread = one (n,k). Warp = one n, k=0..31 -> coalesced 128B stores per l.

#define NPTS   65536
#define KMAX   32
#define LMAX   32
#define LSTART 49   // L_MAX + int(sqrt(10*L_MAX)) = 32 + 17
#define BLK    256
#define NCHUNK (NPTS / 8)   // 8192 chunks of 8 n each
#define GRID   740          // 5 blocks/SM * 148 SMs

// a + b and a - b as FFMA with immediate +-1.0 multiplier.
__device__ __forceinline__ float fa(float a, float b) {
    float d; asm("fma.rn.f32 %0,%1,0f3F800000,%2;" : "=f"(d) : "f"(a), "f"(b)); return d;
}
__device__ __forceinline__ float fs(float a, float b) {  // a - b
    float d; asm("fma.rn.f32 %0,%1,0fBF800000,%2;" : "=f"(d) : "f"(b), "f"(a)); return d;
}

__global__ void __launch_bounds__(BLK, 5)
sph_bessel_pst(const float* __restrict__ r, float* __restrict__ out) {
    const int w  = threadIdx.x >> 5;      // local n within chunk
    const int kk = threadIdx.x & 31;      // k = kk+1
    const float kf = (float)(kk + 1);

    int c = blockIdx.x;
    float rv = __ldg(&r[c * 8 + w]);      // first chunk's r

    for (; c < NCHUNK; ) {
        const int n = c * 8 + w;

        // exact DS x = r*k
        float xh = rv * kf;
        float xl = fmaf(rv, kf, -xh);

        // sigma = 0.25 / 2^floor(log2 max(x,99)) via exponent bits (exact pow2)
        float m = fmaxf(xh, 99.0f);
        int pb = __float_as_int(m) & 0x7f800000;
        float sigma = __int_as_float(0x7E000000 - pb);

        // z = x*sigma (exact), X2 = z^2 as DS
        float zh = xh * sigma, zl = xl * sigma;
        float X2h = zh * zh;
        float X2l = fmaf(zh, zh, -X2h);
        X2l = fmaf(zh, 2.0f * zl, X2l);
        X2l = fmaf(zl, zl, X2l);

        // state: A = S_l, B = S_{l+1}, unnormalized DS pairs. Init (2^70, 0).
        float Ah = 0x1p70f, Al = 0.0f, Bh = 0.0f, Bl = 0.0f;
        float y[LMAX];
        float y0 = 0.0f;

        #pragma unroll
        for (int i = LSTART; i >= 1; --i) {
            float cs = (float)(2 * i + 1) * sigma;   // exact (int<=99 * pow2)

            // t = cs (x) A   (DS product, exact residual)
            float th = cs * Ah;
            float te = fmaf(cs, Ah, -th);
            te = fmaf(cs, Al, te);

            // u = X2 (x) B
            float uh = X2h * Bh;
            float ue = fmaf(X2h, Bh, -uh);
            ue = fmaf(X2h, Bl, ue);
            ue = fmaf(X2l, Bh, ue);

            // C = t - u : branchless Knuth two-sum of (th, -uh)
            float sh = fs(th, uh);
            float v  = fs(sh, th);
            float ww = fs(sh, v);
            float e1 = fs(th, ww);
            float t1 = fa(uh, v);
            float er = fs(e1, t1);
            float lo = fa(er, te);
            lo = fs(lo, ue);

            Bh = Ah; Bl = Al;
            Ah = sh; Al = lo;

            if (i == 1)         y0 = fa(sh, lo);   // DS-rounded: feeds 1/y0
            else if (i <= LMAX) y[i - 1] = sh;     // reg tap (rename, free)
        }
        y[0] = y0;

        // prefetch next chunk's r (hidden behind epilogue)
        c += GRID;
        if (c < NCHUNK) rv = __ldg(&r[c * 8 + w]);

        // normalization: true j0 = sin(x)/x (MUFU), x_lo phase compensation.
        float s, cc;
        __sincosf(xh, &s, &cc);
        s = fmaf(xl, cc, s);
        float norm = __fdividef(s * (0.7978845608028654f * kf), xh * y0);

        // even/odd z^l chains (halved serial latency)
        float zh2 = zh * zh;
        float ne = norm;                   // for even l
        float no = norm * zh;              // for odd l

        float* o = out + (size_t)n * (LMAX * KMAX) + kk;
        #pragma unroll
        for (int l = 0; l < LMAX; l += 2) {
            o[(size_t)l * KMAX]       = y[l]     * ne;   // coalesced 128B
            o[(size_t)(l + 1) * KMAX] = y[l + 1] * no;
            ne *= zh2;
            no *= zh2;
        }
    }
}

extern "C" void kernel_launch(void* const* d_in, const int* in_sizes, int n_in,
                              void* d_out, int out_size) {
    const float* r = (const float*)d_in[0];
    float* out = (float*)d_out;
    sph_bessel_pst<<<GRID, BLK>>>(r, out);
}

// round 14
// speedup vs baseline: 1.0376x; 1.0376x over previous
#include <cuda_runtime.h>

// SphericalBessel: two-pass outlier-aware scheme.
//
// The float64 reference's global-norm error is dominated by rows where the
// Miller trajectory's y0 ~ 0 (normalization divides by it; amplification up
// to ~2e6). Pass 1 computes ALL rows in cheap fp32 (3 FFMA/step) and flags
// rows with |y0| < 3% of the local envelope (zeros of j0/j1/j2 interlace ->
// envelope = max(|y1|z,|y2|z^2,|y3|z^3) is a safe estimate). Pass 2 reruns
// only flagged rows (~2%) with the proven double-single core + accurate
// sincosf and overwrites them. Unflagged rows: amplification <= 33x on a
// ~1e-6 fp32 trajectory error, and their share of the outlier-dominated
// norm is negligible.

#define NPTS   65536
#define KMAX   32
#define LMAX   32
#define LSTART 49   // L_MAX + int(sqrt(10*L_MAX)) = 32 + 17
#define BLK    256

__device__ int g_count;
__device__ int g_list[NPTS * KMAX];      // capacity = all ids: cannot overflow

// a + b and a - b as FFMA with immediate +-1.0 multiplier.
__device__ __forceinline__ float fa(float a, float b) {
    float d; asm("fma.rn.f32 %0,%1,0f3F800000,%2;" : "=f"(d) : "f"(a), "f"(b)); return d;
}
__device__ __forceinline__ float fs(float a, float b) {  // a - b
    float d; asm("fma.rn.f32 %0,%1,0fBF800000,%2;" : "=f"(d) : "f"(b), "f"(a)); return d;
}

__global__ void zero_count() { g_count = 0; }

// ---------------- Pass 1: fp32 everywhere + flagging ----------------
__global__ void __launch_bounds__(BLK)
sph_pass1(const float* __restrict__ r, float* __restrict__ out) {
    int tid = blockIdx.x * BLK + threadIdx.x;
    int n  = tid >> 5;
    int kk = tid & 31;                    // k = kk+1
    float kf = (float)(kk + 1);
    float rv = __ldg(&r[n]);

    float xh = rv * kf;
    float xl = fmaf(rv, kf, -xh);         // exact DS x (for sin phase comp)

    // sigma = 0.25 / 2^floor(log2 max(x,99))  (exact pow2)
    float m = fmaxf(xh, 99.0f);
    int pb = __float_as_int(m) & 0x7f800000;
    float sigma = __int_as_float(0x7E000000 - pb);

    float zh = xh * sigma;
    float nX2h = -(zh * zh);

    // fp32 recurrence: 3 ops/step
    float A = 0x1p70f, B = 0.0f;
    float y[LMAX];
    #pragma unroll
    for (int i = LSTART; i >= 1; --i) {
        float cs = (float)(2 * i + 1) * sigma;
        float C  = fmaf(nX2h, B, cs * A);
        B = A; A = C;
        if (i <= LMAX) y[i - 1] = C;
    }

    // danger flag: |y0| < 3% of local envelope (T_l = y_l * z^l)
    float t1 = fabsf(y[1]) * zh;
    float t2 = fabsf(y[2]) * zh;          // will multiply by zh again
    float t3 = fabsf(y[3]) * zh;
    float amp = fmaxf(t1, fmaxf(t2 * zh, t3 * zh * zh));
    bool danger = fabsf(y[0]) < 0.03f * amp;

    // warp-aggregated compaction of flagged ids
    unsigned msk = __ballot_sync(0xffffffffu, danger);
    int base = 0;
    int leader = __ffs(msk) - 1;
    if (msk) {
        if ((int)(threadIdx.x & 31) == leader)
            base = atomicAdd(&g_count, __popc(msk));
        base = __shfl_sync(0xffffffffu, base, leader);
        if (danger) {
            int rank = __popc(msk & ((1u << (threadIdx.x & 31)) - 1u));
            g_list[base + rank] = tid;
        }
    }

    // normalization (fp32/MUFU; flagged rows get overwritten by pass 2)
    float s, cc;
    __sincosf(xh, &s, &cc);
    s = fmaf(xl, cc, s);
    float norm = __fdividef(s * (0.7978845608028654f * kf), xh * y[0]);

    float zh2 = zh * zh;
    float ne = norm, no = norm * zh;
    float* o = out + (size_t)n * (LMAX * KMAX) + kk;
    #pragma unroll
    for (int l = 0; l < LMAX; l += 2) {
        o[(size_t)l * KMAX]       = y[l]     * ne;   // coalesced 128B per l
        o[(size_t)(l + 1) * KMAX] = y[l + 1] * no;
        ne *= zh2; no *= zh2;
    }
}

// ---------------- Pass 2: DS rerun of flagged rows ----------------
__global__ void __launch_bounds__(BLK)
sph_pass2(const float* __restrict__ r, float* __restrict__ out) {
    int cnt = g_count;
    for (int t = blockIdx.x * BLK + threadIdx.x; t < cnt; t += gridDim.x * BLK) {
        int id = g_list[t];
        int n  = id >> 5;
        int kk = id & 31;
        float kf = (float)(kk + 1);
        float rv = __ldg(&r[n]);

        float xh = rv * kf;
        float xl = fmaf(rv, kf, -xh);

        float m = fmaxf(xh, 99.0f);
        int pb = __float_as_int(m) & 0x7f800000;
        float sigma = __int_as_float(0x7E000000 - pb);

        float zh = xh * sigma, zl = xl * sigma;
        float X2h = zh * zh;
        float X2l = fmaf(zh, zh, -X2h);
        X2l = fmaf(zh, 2.0f * zl, X2l);
        X2l = fmaf(zl, zl, X2l);

        float Ah = 0x1p70f, Al = 0.0f, Bh = 0.0f, Bl = 0.0f;
        float y[LMAX];
        float y0 = 0.0f;

        #pragma unroll
        for (int i = LSTART; i >= 1; --i) {
            float cs = (float)(2 * i + 1) * sigma;

            float th = cs * Ah;
            float te = fmaf(cs, Ah, -th);
            te = fmaf(cs, Al, te);

            float uh = X2h * Bh;
            float ue = fmaf(X2h, Bh, -uh);
            ue = fmaf(X2h, Bl, ue);
            ue = fmaf(X2l, Bh, ue);

            float sh = fs(th, uh);
            float v  = fs(sh, th);
            float ww = fs(sh, v);
            float e1 = fs(th, ww);
            float tt = fa(uh, v);
            float er = fs(e1, tt);
            float lo = fa(er, te);
            lo = fs(lo, ue);

            Bh = Ah; Bl = Al;
            Ah = sh; Al = lo;

            if (i == 1) y0 = fa(sh, lo);
            else if (i <= LMAX) y[i - 1] = sh;
        }
        y[0] = y0;

        // accurate normalization (full sincosf + DS phase compensation)
        float s, cc;
        sincosf(xh, &s, &cc);
        s = fmaf(xl, cc, s);
        float norm = (s / xh) * (0.7978845608028654f * kf) / y0;

        float zh2 = zh * zh;
        float ne = norm, no = norm * zh;
        float* o = out + (size_t)n * (LMAX * KMAX) + kk;
        #pragma unroll
        for (int l = 0; l < LMAX; l += 2) {
            o[(size_t)l * KMAX]       = y[l]     * ne;
            o[(size_t)(l + 1) * KMAX] = y[l + 1] * no;
            ne *= zh2; no *= zh2;
        }
    }
}

extern "C" void kernel_launch(void* const* d_in, const int* in_sizes, int n_in,
                              void* d_out, int out_size) {
    const float* r = (const float*)d_in[0];
    float* out = (float*)d_out;
    zero_count<<<1, 1>>>();
    sph_pass1<<<NPTS * KMAX / BLK, BLK>>>(r, out);
    sph_pass2<<<512, BLK>>>(r, out);
}